// round 12
// baseline (speedup 1.0000x reference)
#include <cuda_runtime.h>
#include <cstdint>

// out[b,k] = sum_ij in1[b,i]*in2[b,j]*cb[k,ij]
// R10 winner (constant-port meta, fixed-4-nnz fully unrolled contraction,
// chunked O + coalesced division-free flush) + coalesced input staging via
// shared. R11 bug fixed: staging buffers must be 16B-aligned in SHARED space
// (O starts at float offset 13041 = byte 52164, only 4B-aligned) -> stage at
// float offset 13044 inside the O region.

#define NK     81
#define NIJ    81
#define TPB    160
#define STRIDE 161       // odd -> conflict-free columns and transpose
#define CHUNK  27
#define NPH    3

#define STAGE_OFF 13044  // ((NIJ*STRIDE + 3) & ~3): 16B-aligned, inside O region
// staging needs 2*TPB*9 = 2880 floats; O region spans [13041, 17388) -> fits.

struct Tbl {
    float4 meta[NK][2];   // per k: {idx_bytes0,w0,idx_bytes1,w1} x2 = 4 nnz
    int    ovp[NPH + 1];  // overflow rowptr per phase
    int    pad[4];
};

__device__ Tbl    g_stage;
__device__ float4 g_ovf[NK * NIJ];   // {o_bytes, q_bytes, w, 0}
__constant__ Tbl  c_tbl;

__global__ void prep_kernel(const float* __restrict__ cb) {
    __shared__ int ocnt[NK];
    __shared__ int ooff[NK + 1];
    const int k = threadIdx.x;
    if (k < NK) {
        int c = 0;
        for (int ij = 0; ij < NIJ; ij++)
            if (cb[k * NIJ + ij] != 0.f) c++;
        ocnt[k] = (c > 4) ? (c - 4) : 0;
    }
    __syncthreads();
    if (k == 0) {
        int s = 0;
        for (int q = 0; q < NK; q++) { ooff[q] = s; s += ocnt[q]; }
        ooff[NK] = s;
        g_stage.ovp[0] = 0;
        g_stage.ovp[1] = ooff[1 * CHUNK];
        g_stage.ovp[2] = ooff[2 * CHUNK];
        g_stage.ovp[3] = s;              // k-ascending -> phase-contiguous
    }
    __syncthreads();
    if (k < NK) {
        float id[4] = {0.f, 0.f, 0.f, 0.f};
        float w [4] = {0.f, 0.f, 0.f, 0.f};
        int n = 0;
        int o = ooff[k];
        const int kl = k % CHUNK;        // row index inside its phase chunk
        for (int ij = 0; ij < NIJ; ij++) {
            float v = cb[k * NIJ + ij];
            if (v != 0.f) {
                if (n < 4) { id[n] = __int_as_float(ij * STRIDE * 4); w[n] = v; n++; }
                else g_ovf[o++] = make_float4(__int_as_float(kl * STRIDE * 4),
                                              __int_as_float(ij * STRIDE * 4), v, 0.f);
            }
        }
        g_stage.meta[k][0] = make_float4(id[0], w[0], id[1], w[1]);
        g_stage.meta[k][1] = make_float4(id[2], w[2], id[3], w[3]);
    }
}

__global__ void __launch_bounds__(TPB, 3) tp_kernel(
    const float* __restrict__ in1,
    const float* __restrict__ in2,
    float* __restrict__ out,
    int B)
{
    extern __shared__ float smem[];
    float* P = smem;                       // NIJ * STRIDE floats
    float* O = smem + NIJ * STRIDE;        // CHUNK * STRIDE floats (4347)
    float* in1s = smem + STAGE_OFF;        // 16B-aligned staging inside O region
    float* in2s = in1s + TPB * 9;          // 1440 floats later: still 16B-aligned

    const int t = threadIdx.x;
    const int base = blockIdx.x * TPB;

    // ---- coalesced input staging ----
    int avail = B * 9 - base * 9;
    if (avail >= TPB * 9) {
        const float4* v1 = (const float4*)(in1 + base * 9);   // base*36 % 16 == 0
        const float4* v2 = (const float4*)(in2 + base * 9);
        float4* s1 = (float4*)in1s;
        float4* s2 = (float4*)in2s;
#pragma unroll
        for (int q = t; q < (TPB * 9) / 4; q += TPB) { s1[q] = v1[q]; s2[q] = v2[q]; }
    } else {                                // tail CTA: scalar + zero-pad
        for (int q = t; q < TPB * 9; q += TPB) {
            bool ok = q < avail;
            in1s[q] = ok ? in1[base * 9 + q] : 0.f;
            in2s[q] = ok ? in2[base * 9 + q] : 0.f;
        }
    }
    __syncthreads();

    float a[9], c9[9];
#pragma unroll
    for (int i = 0; i < 9; i++) { a[i] = in1s[t * 9 + i]; c9[i] = in2s[t * 9 + i]; }
    __syncthreads();          // inputs consumed; O region free for contraction

    // outer product into own shared column (only this thread reads it)
    char* Pb = (char*)P + t * 4;
#pragma unroll
    for (int i = 0; i < 9; i++)
#pragma unroll
        for (int j = 0; j < 9; j++)
            *(float*)(Pb + (i * 9 + j) * STRIDE * 4) = a[i] * c9[j];

    const int limit  = B * NK;                   // 84,934,656 < 2^31
    const int gbase0 = blockIdx.x * TPB * NK;
    char* Ob = (char*)O + t * 4;

#pragma unroll
    for (int ph = 0; ph < NPH; ph++) {
        // ---- contraction: fixed 4 nnz per k, immediate constant addresses ----
#pragma unroll
        for (int kq = 0; kq < CHUNK; kq++) {
            const float4 m0 = c_tbl.meta[ph * CHUNK + kq][0];
            const float4 m1 = c_tbl.meta[ph * CHUNK + kq][1];
            float s0 = m0.y * (*(const float*)(Pb + __float_as_int(m0.x)));
            float s1 = m0.w * (*(const float*)(Pb + __float_as_int(m0.z)));
            s0 = fmaf(m1.y, *(const float*)(Pb + __float_as_int(m1.x)), s0);
            s1 = fmaf(m1.w, *(const float*)(Pb + __float_as_int(m1.z)), s1);
            *(float*)(Ob + kq * STRIDE * 4) = s0 + s1;
        }
        // ---- rare overflow entries (rows with >4 nnz), own-column += ----
        {
            const int r1 = c_tbl.ovp[ph + 1];
#pragma unroll 1
            for (int r = c_tbl.ovp[ph]; r < r1; r++) {
                const float4 e = g_ovf[r];
                float* op = (float*)(Ob + __float_as_int(e.x));
                *op = fmaf(e.z, *(const float*)(Pb + __float_as_int(e.y)), *op);
            }
        }
        __syncthreads();   // flush reads other threads' O columns

        // ---- coalesced flush, division-free incremental indexing ----
        {
            int bl = t / CHUNK;
            int kq = t - bl * CHUNK;
            int gi = bl * NK + kq;
            int si = kq * STRIDE + bl;
            const int gb = gbase0 + ph * CHUNK;
#pragma unroll
            for (int rr = 0; rr < CHUNK; rr++) {
                int g = gb + gi;
                if (g < limit) out[g] = O[si];
                kq += 25;                         // advance slot by TPB=160
                if (kq >= CHUNK) {
                    kq -= CHUNK;
                    gi += 5 * NK + 25 + (NK - CHUNK);             // 484
                    si += 25 * STRIDE + 5 - (CHUNK * STRIDE - 1); // -316
                } else {
                    gi += 5 * NK + 25;                            // 430
                    si += 25 * STRIDE + 5;                        // 4030
                }
            }
        }
        __syncthreads();   // next phase reuses O
    }
}

extern "C" void kernel_launch(void* const* d_in, const int* in_sizes, int n_in,
                              void* d_out, int out_size) {
    const float* in1 = (const float*)d_in[0];
    const float* in2 = (const float*)d_in[1];
    const float* cb  = (const float*)d_in[2];
    float* out = (float*)d_out;

    const int B = in_sizes[0] / 9;

    const size_t smem_bytes =
        (size_t)(NIJ * STRIDE) * sizeof(float) +     // P  52,164
        (size_t)(CHUNK * STRIDE) * sizeof(float);    // O  17,388  -> 69,552 B, 3 CTAs/SM

    cudaFuncSetAttribute(tp_kernel,
                         cudaFuncAttributeMaxDynamicSharedMemorySize,
                         (int)smem_bytes);

    prep_kernel<<<1, 96>>>(cb);

    void *dst = nullptr, *src = nullptr;
    cudaGetSymbolAddress(&dst, c_tbl);
    cudaGetSymbolAddress(&src, g_stage);
    cudaMemcpyAsync(dst, src, sizeof(Tbl), cudaMemcpyDeviceToDevice, 0);

    tp_kernel<<<(B + TPB - 1) / TPB, TPB, smem_bytes>>>(in1, in2, out, B);
}

// round 13
// speedup vs baseline: 1.0136x; 1.0136x over previous
#include <cuda_runtime.h>
#include <cuda_fp16.h>
#include <cstdint>

// out[b,k] = sum_ij in1[b,i]*in2[b,j]*cb[k,ij]
// R10 winner + P stored in fp16 (half smem -> 5 CTAs/SM = 25 warps vs 15).
// P layout: half, addr = ij*TPB + t (fixed ij -> consecutive t, conflict-free;
// half-pairs share a 4B word = same-word access, no conflict). Gathers are
// LDS.U16 + CVT + FFMA. Error budget: fp16 product rounding ~4.9e-4/term ->
// global rel_err ~3e-4 << 1e-3 threshold. O stays fp32 (stride 161 transpose).

#define NK     81
#define NIJ    81
#define TPB    160
#define OSTR   161       // O stride (odd -> conflict-free transpose flush)
#define CHUNK  27
#define NPH    3

#define P_BYTES   (NIJ * TPB * 2)          // 25,920
#define SMEM_TOT  (P_BYTES + CHUNK * OSTR * 4)   // + 17,388 = 43,308

struct Tbl {
    float4 meta[NK][2];   // per k: {ij_halfbyteoff0,w0,off1,w1} x2 = 4 nnz
    int    ovp[NPH + 1];  // overflow rowptr per phase
    int    pad[4];
};

__device__ Tbl    g_stage;
__device__ float4 g_ovf[NK * NIJ];   // {o_bytes(O fp32), p_bytes(P fp16), w, 0}
__constant__ Tbl  c_tbl;

__global__ void prep_kernel(const float* __restrict__ cb) {
    __shared__ int ocnt[NK];
    __shared__ int ooff[NK + 1];
    const int k = threadIdx.x;
    if (k < NK) {
        int c = 0;
        for (int ij = 0; ij < NIJ; ij++)
            if (cb[k * NIJ + ij] != 0.f) c++;
        ocnt[k] = (c > 4) ? (c - 4) : 0;
    }
    __syncthreads();
    if (k == 0) {
        int s = 0;
        for (int q = 0; q < NK; q++) { ooff[q] = s; s += ocnt[q]; }
        ooff[NK] = s;
        g_stage.ovp[0] = 0;
        g_stage.ovp[1] = ooff[1 * CHUNK];
        g_stage.ovp[2] = ooff[2 * CHUNK];
        g_stage.ovp[3] = s;              // k-ascending -> phase-contiguous
    }
    __syncthreads();
    if (k < NK) {
        float id[4] = {0.f, 0.f, 0.f, 0.f};
        float w [4] = {0.f, 0.f, 0.f, 0.f};
        int n = 0;
        int o = ooff[k];
        const int kl = k % CHUNK;
        for (int ij = 0; ij < NIJ; ij++) {
            float v = cb[k * NIJ + ij];
            if (v != 0.f) {
                if (n < 4) { id[n] = __int_as_float(ij * TPB * 2); w[n] = v; n++; }
                else g_ovf[o++] = make_float4(__int_as_float(kl * OSTR * 4),
                                              __int_as_float(ij * TPB * 2), v, 0.f);
            }
        }
        g_stage.meta[k][0] = make_float4(id[0], w[0], id[1], w[1]);
        g_stage.meta[k][1] = make_float4(id[2], w[2], id[3], w[3]);
    }
}

__global__ void __launch_bounds__(TPB, 5) tp_kernel(
    const float* __restrict__ in1,
    const float* __restrict__ in2,
    float* __restrict__ out,
    int B)
{
    extern __shared__ char smemc[];
    __half* P = (__half*)smemc;                    // NIJ * TPB halves
    float*  O = (float*)(smemc + P_BYTES);         // CHUNK * OSTR floats

    const int t = threadIdx.x;
    const int b = blockIdx.x * TPB + t;

    float a[9], c9[9];
    if (b < B) {
#pragma unroll
        for (int i = 0; i < 9; i++) a[i]  = __ldg(&in1[b * 9 + i]);
#pragma unroll
        for (int j = 0; j < 9; j++) c9[j] = __ldg(&in2[b * 9 + j]);
    } else {
#pragma unroll
        for (int i = 0; i < 9; i++) { a[i] = 0.f; c9[i] = 0.f; }
    }

    // outer product -> fp16, own column (only this thread reads it; no sync)
    char* Pb = (char*)P + t * 2;
#pragma unroll
    for (int i = 0; i < 9; i++)
#pragma unroll
        for (int j = 0; j < 9; j++)
            *(__half*)(Pb + (i * 9 + j) * (TPB * 2)) = __float2half_rn(a[i] * c9[j]);

    const int limit  = B * NK;                   // 84,934,656 < 2^31
    const int gbase0 = blockIdx.x * TPB * NK;
    char* Ob = (char*)O + t * 4;

#pragma unroll
    for (int ph = 0; ph < NPH; ph++) {
        // ---- contraction: fixed 4 nnz per k, immediate constant addresses ----
#pragma unroll
        for (int kq = 0; kq < CHUNK; kq++) {
            const float4 m0 = c_tbl.meta[ph * CHUNK + kq][0];
            const float4 m1 = c_tbl.meta[ph * CHUNK + kq][1];
            float p0 = __half2float(*(const __half*)(Pb + __float_as_int(m0.x)));
            float p1 = __half2float(*(const __half*)(Pb + __float_as_int(m0.z)));
            float p2 = __half2float(*(const __half*)(Pb + __float_as_int(m1.x)));
            float p3 = __half2float(*(const __half*)(Pb + __float_as_int(m1.z)));
            float s0 = m0.y * p0;
            float s1 = m0.w * p1;
            s0 = fmaf(m1.y, p2, s0);
            s1 = fmaf(m1.w, p3, s1);
            *(float*)(Ob + kq * OSTR * 4) = s0 + s1;
        }
        // ---- rare overflow entries (rows with >4 nnz), own-column += ----
        {
            const int r1 = c_tbl.ovp[ph + 1];
#pragma unroll 1
            for (int r = c_tbl.ovp[ph]; r < r1; r++) {
                const float4 e = g_ovf[r];
                float pv = __half2float(*(const __half*)(Pb + __float_as_int(e.y)));
                float* op = (float*)(Ob + __float_as_int(e.x));
                *op = fmaf(e.z, pv, *op);
            }
        }
        __syncthreads();   // flush reads other threads' O columns

        // ---- coalesced flush, division-free incremental indexing ----
        {
            int bl = t / CHUNK;
            int kq = t - bl * CHUNK;
            int gi = bl * NK + kq;
            int si = kq * OSTR + bl;
            const int gb = gbase0 + ph * CHUNK;
#pragma unroll
            for (int rr = 0; rr < CHUNK; rr++) {
                int g = gb + gi;
                if (g < limit) out[g] = O[si];
                kq += 25;                         // advance slot by TPB=160
                if (kq >= CHUNK) {
                    kq -= CHUNK;
                    gi += 5 * NK + 25 + (NK - CHUNK);             // 484
                    si += 25 * OSTR + 5 - (CHUNK * OSTR - 1);     // -316
                } else {
                    gi += 5 * NK + 25;                            // 430
                    si += 25 * OSTR + 5;                          // 4030
                }
            }
        }
        __syncthreads();   // next phase reuses O
    }
}

extern "C" void kernel_launch(void* const* d_in, const int* in_sizes, int n_in,
                              void* d_out, int out_size) {
    const float* in1 = (const float*)d_in[0];
    const float* in2 = (const float*)d_in[1];
    const float* cb  = (const float*)d_in[2];
    float* out = (float*)d_out;

    const int B = in_sizes[0] / 9;

    cudaFuncSetAttribute(tp_kernel,
                         cudaFuncAttributeMaxDynamicSharedMemorySize,
                         SMEM_TOT);      // 43,308 B -> 5 CTAs/SM

    prep_kernel<<<1, 96>>>(cb);

    void *dst = nullptr, *src = nullptr;
    cudaGetSymbolAddress(&dst, c_tbl);
    cudaGetSymbolAddress(&src, g_stage);
    cudaMemcpyAsync(dst, src, sizeof(Tbl), cudaMemcpyDeviceToDevice, 0);

    tp_kernel<<<(B + TPB - 1) / TPB, TPB, SMEM_TOT>>>(in1, in2, out, B);
}

// round 14
// speedup vs baseline: 1.0324x; 1.0186x over previous
#include <cuda_runtime.h>
#include <cuda_fp16.h>
#include <cstdint>

// out[b,k] = sum_ij in1[b,i]*in2[b,j]*cb[k,ij]
// R13 + (a) coalesced input staging through the P region (16B-aligned, read
// before P overwrites it), (b) O staged in fp16 with stride 162 halves
// (conflict-free transpose: bank step 17, gcd(17,32)=1) -> smem 34,668 B ->
// 6 CTAs/SM = 30 warps. Meta on the constant port, fixed 4 nnz/k unrolled,
// overflow list for >4-nnz rows. Error: fp16 P (~2e-4) + fp16 O (~2.4e-4)
// -> ~3.2e-4 global, under the 1e-3 threshold.

#define NK     81
#define NIJ    81
#define TPB    160
#define OSTR   162       // O stride in HALVES (byte stride 324)
#define CHUNK  27
#define NPH    3

#define P_BYTES  (NIJ * TPB * 2)                 // 25,920 (16B-aligned size)
#define O_BYTES  (CHUNK * OSTR * 2)              // 8,748
#define SMEM_TOT (P_BYTES + O_BYTES)             // 34,668 -> 6 CTAs/SM

struct Tbl {
    float4 meta[NK][2];   // per k: {P_halfbyteoff0,w0,off1,w1} x2 = 4 nnz
    int    ovp[NPH + 1];  // overflow rowptr per phase
    int    pad[4];
};

__device__ Tbl    g_stage;
__device__ float4 g_ovf[NK * NIJ];   // {o_bytes(O fp16 row), p_bytes(P fp16), w, 0}
__constant__ Tbl  c_tbl;

__global__ void prep_kernel(const float* __restrict__ cb) {
    __shared__ int ocnt[NK];
    __shared__ int ooff[NK + 1];
    const int k = threadIdx.x;
    if (k < NK) {
        int c = 0;
        for (int ij = 0; ij < NIJ; ij++)
            if (cb[k * NIJ + ij] != 0.f) c++;
        ocnt[k] = (c > 4) ? (c - 4) : 0;
    }
    __syncthreads();
    if (k == 0) {
        int s = 0;
        for (int q = 0; q < NK; q++) { ooff[q] = s; s += ocnt[q]; }
        ooff[NK] = s;
        g_stage.ovp[0] = 0;
        g_stage.ovp[1] = ooff[1 * CHUNK];
        g_stage.ovp[2] = ooff[2 * CHUNK];
        g_stage.ovp[3] = s;              // k-ascending -> phase-contiguous
    }
    __syncthreads();
    if (k < NK) {
        float id[4] = {0.f, 0.f, 0.f, 0.f};
        float w [4] = {0.f, 0.f, 0.f, 0.f};
        int n = 0;
        int o = ooff[k];
        const int kl = k % CHUNK;
        for (int ij = 0; ij < NIJ; ij++) {
            float v = cb[k * NIJ + ij];
            if (v != 0.f) {
                if (n < 4) { id[n] = __int_as_float(ij * TPB * 2); w[n] = v; n++; }
                else g_ovf[o++] = make_float4(__int_as_float(kl * OSTR * 2),
                                              __int_as_float(ij * TPB * 2), v, 0.f);
            }
        }
        g_stage.meta[k][0] = make_float4(id[0], w[0], id[1], w[1]);
        g_stage.meta[k][1] = make_float4(id[2], w[2], id[3], w[3]);
    }
}

__global__ void __launch_bounds__(TPB, 6) tp_kernel(
    const float* __restrict__ in1,
    const float* __restrict__ in2,
    float* __restrict__ out,
    int B)
{
    extern __shared__ char smemc[];
    __half* P   = (__half*)smemc;                  // NIJ * TPB halves
    __half* Oh  = (__half*)(smemc + P_BYTES);      // CHUNK * OSTR halves
    float*  st1 = (float*)smemc;                   // input staging (P region)
    float*  st2 = (float*)(smemc + TPB * 9 * 4);   // offset 5760, 16B-aligned

    const int t = threadIdx.x;
    const int base = blockIdx.x * TPB;

    // ---- coalesced input staging into the (not-yet-used) P region ----
    const int avail = B * 9 - base * 9;
    if (avail >= TPB * 9) {
        const float4* v1 = (const float4*)(in1 + base * 9);  // base*36 % 16 == 0
        const float4* v2 = (const float4*)(in2 + base * 9);
        float4* s1 = (float4*)st1;
        float4* s2 = (float4*)st2;
#pragma unroll
        for (int q = t; q < (TPB * 9) / 4; q += TPB) { s1[q] = v1[q]; s2[q] = v2[q]; }
    } else {                                // tail CTA: scalar + zero-pad
        for (int q = t; q < TPB * 9; q += TPB) {
            bool ok = q < avail;
            st1[q] = ok ? in1[base * 9 + q] : 0.f;
            st2[q] = ok ? in2[base * 9 + q] : 0.f;
        }
    }
    __syncthreads();

    float a[9], c9[9];                      // bank = 9t+i mod 32, gcd(9,32)=1
#pragma unroll
    for (int i = 0; i < 9; i++) { a[i] = st1[t * 9 + i]; c9[i] = st2[t * 9 + i]; }
    __syncthreads();                        // staging consumed; P region free

    // outer product -> fp16 P, own column (only this thread reads it)
    char* Pb = (char*)P + t * 2;
#pragma unroll
    for (int i = 0; i < 9; i++)
#pragma unroll
        for (int j = 0; j < 9; j++)
            *(__half*)(Pb + (i * 9 + j) * (TPB * 2)) = __float2half_rn(a[i] * c9[j]);

    const int limit  = B * NK;                   // 84,934,656 < 2^31
    const int gbase0 = blockIdx.x * TPB * NK;
    char* Ob = (char*)Oh + t * 2;

#pragma unroll
    for (int ph = 0; ph < NPH; ph++) {
        // ---- contraction: fixed 4 nnz per k, immediate constant addresses ----
#pragma unroll
        for (int kq = 0; kq < CHUNK; kq++) {
            const float4 m0 = c_tbl.meta[ph * CHUNK + kq][0];
            const float4 m1 = c_tbl.meta[ph * CHUNK + kq][1];
            float p0 = __half2float(*(const __half*)(Pb + __float_as_int(m0.x)));
            float p1 = __half2float(*(const __half*)(Pb + __float_as_int(m0.z)));
            float p2 = __half2float(*(const __half*)(Pb + __float_as_int(m1.x)));
            float p3 = __half2float(*(const __half*)(Pb + __float_as_int(m1.z)));
            float s0 = m0.y * p0;
            float s1 = m0.w * p1;
            s0 = fmaf(m1.y, p2, s0);
            s1 = fmaf(m1.w, p3, s1);
            *(__half*)(Ob + kq * (OSTR * 2)) = __float2half_rn(s0 + s1);
        }
        // ---- rare overflow entries (rows with >4 nnz), own-column += ----
        {
            const int r1 = c_tbl.ovp[ph + 1];
#pragma unroll 1
            for (int r = c_tbl.ovp[ph]; r < r1; r++) {
                const float4 e = g_ovf[r];
                float pv = __half2float(*(const __half*)(Pb + __float_as_int(e.y)));
                __half* op = (__half*)(Ob + __float_as_int(e.x));
                *op = __float2half_rn(fmaf(e.z, pv, __half2float(*op)));
            }
        }
        __syncthreads();   // flush reads other threads' O columns

        // ---- coalesced flush, division-free incremental indexing ----
        {
            int bl = t / CHUNK;
            int kq = t - bl * CHUNK;
            int gi = bl * NK + kq;
            int si = kq * OSTR + bl;        // half units
            const int gb = gbase0 + ph * CHUNK;
#pragma unroll
            for (int rr = 0; rr < CHUNK; rr++) {
                int g = gb + gi;
                if (g < limit) out[g] = __half2float(Oh[si]);
                kq += 25;                         // advance slot by TPB=160
                if (kq >= CHUNK) {
                    kq -= CHUNK;
                    gi += 5 * NK + 25 + (NK - CHUNK);        // 484
                    si += 25 * OSTR + 5 - (CHUNK * OSTR - 1);// 4055 - 4373 = -318
                } else {
                    gi += 5 * NK + 25;                       // 430
                    si += 25 * OSTR + 5;                     // 4055
                }
            }
        }
        __syncthreads();   // next phase reuses O
    }
}

extern "C" void kernel_launch(void* const* d_in, const int* in_sizes, int n_in,
                              void* d_out, int out_size) {
    const float* in1 = (const float*)d_in[0];
    const float* in2 = (const float*)d_in[1];
    const float* cb  = (const float*)d_in[2];
    float* out = (float*)d_out;

    const int B = in_sizes[0] / 9;

    cudaFuncSetAttribute(tp_kernel,
                         cudaFuncAttributeMaxDynamicSharedMemorySize,
                         SMEM_TOT);      // 34,668 B -> 6 CTAs/SM

    prep_kernel<<<1, 96>>>(cb);

    void *dst = nullptr, *src = nullptr;
    cudaGetSymbolAddress(&dst, c_tbl);
    cudaGetSymbolAddress(&src, g_stage);
    cudaMemcpyAsync(dst, src, sizeof(Tbl), cudaMemcpyDeviceToDevice, 0);

    tp_kernel<<<(B + TPB - 1) / TPB, TPB, SMEM_TOT>>>(in1, in2, out, B);
}